// round 16
// baseline (speedup 1.0000x reference)
#include <cuda_runtime.h>
#include <cuda_fp16.h>
#include <math.h>
#include <stdint.h>

#define Bn 16
#define Nn 256
#define Fn 64
#define Hn 128
#define D_MAX 1.7320508f
#define NODES 64
#define NR 13   // Chebyshev terms r = 0..12

__device__ float g_nodes[NODES * Fn];
__device__ float ch_coef[NR * Fn];
__device__ float partial_out[4 * Bn * Nn * Fn];  // per-j-quarter partials

__device__ __forceinline__ float softplus_acc(float x) {
    // matches jax.nn.softplus = logaddexp(x, 0), stable for all x
    return fmaxf(x, 0.0f) + log1pf(expf(-fabsf(x)));
}
__device__ __forceinline__ uint32_t smem_u32(const void* p) {
    uint32_t a;
    asm("{ .reg .u64 t; cvta.to.shared.u64 t, %1; cvt.u32.u64 %0, t; }"
        : "=r"(a) : "l"(p));
    return a;
}

// ---------------------------------------------------------------------------
// K1: g_f at 64 Chebyshev nodes. grid = NODES, block = Hn.
// ---------------------------------------------------------------------------
__global__ void eval_nodes_kernel(const float* __restrict__ w1,
                                  const float* __restrict__ b1,
                                  const float* __restrict__ W2,
                                  const float* __restrict__ b2) {
    __shared__ float u[Hn];
    const int m = blockIdx.x, h = threadIdx.x;
    const float theta = ((float)m + 0.5f) * (3.14159265358979f / (float)NODES);
    const float d = (cosf(theta) + 1.0f) * (D_MAX * 0.5f);
    u[h] = softplus_acc(fmaf(d, w1[h], b1[h]));
    __syncthreads();
    if (h < Fn) {
        float acc = b2[h];
#pragma unroll
        for (int hh = 0; hh < Hn; ++hh)
            acc = fmaf(u[hh], W2[hh * Fn + h], acc);
        g_nodes[m * Fn + h] = softplus_acc(acc);
    }
}

// ---------------------------------------------------------------------------
// K2: DCT fit -> ch_coef[r][f], r = 0..12. 1 block, NR*64 = 832 threads.
// ---------------------------------------------------------------------------
__global__ void dct_kernel() {
    const int tid = threadIdx.x;          // 0..831
    const int r = tid >> 6, ff = tid & 63;
    float s = 0.0f;
    for (int m = 0; m < NODES; ++m) {
        const float theta = ((float)m + 0.5f) * (3.14159265358979f / (float)NODES);
        s += g_nodes[m * Fn + ff] * cosf((float)r * theta);
    }
    ch_coef[tid] = s * ((r == 0) ? (1.0f / NODES) : (2.0f / NODES));
}

// ---------------------------------------------------------------------------
// K3: main HMMA kernel. grid = 128 = b(16) x ih(2) x kh(4), block = 512.
//
//   f_bar_partial[i, f] = sum_{r=0..12} sum_{j in quarter} T_r(xhat_ij) *
//                         (c_rf * F[j, f])
//
// 13 accumulating M=128 N=64 K=64 f16 GEMMs via mma.sync.m16n8k16.
//   A_r (128 x 64 f16): Chebyshev recurrence in registers, double-buffered.
//     Round r writes A_{r+1} = Tc (== T_{r+1}), THEN advances the recurrence.
//   B_r ([f][j] f16 = col-major B): all 13 precomputed in smem.
// 144-byte padded rows -> conflict-free ldmatrix.
// Warp w: rows m0 = (w&7)*16, cols nh = (w>>3)*32; 4 n-tiles of 8.
// ---------------------------------------------------------------------------
__global__ __launch_bounds__(512, 1) void mp_mma_kernel(
    const float* __restrict__ rg, const float* __restrict__ fg) {
    extern __shared__ __align__(16) char sm[];
    __half* smB = (__half*)sm;                      // NR*64 rows * 144B = 119808
    __half* smA0 = (__half*)(sm + 119808);          // 128 rows * 144B = 18432
    __half* smA1 = (__half*)(sm + 138240);          // 18432
    float* Fst = (float*)(sm + 138240);             // staging [f][72] f32 (= A1)
    float* smR = (float*)(sm + 156672);             // 768 floats

    const int tid = threadIdx.x;
    const int wid = tid >> 5, lane = tid & 31;
    const int cta = blockIdx.x;
    const int b = cta >> 3, ih = (cta >> 2) & 1, kh = cta & 3;

    // 1) stage r[b] and the F j-quarter transposed to [f][72] fp32
    for (int e = tid; e < Nn * 3; e += 512) smR[e] = rg[b * Nn * 3 + e];
    for (int e = tid; e < 64 * 64; e += 512) {
        const int j = e >> 6, ff = e & 63;
        Fst[ff * 72 + j] = fg[((size_t)b * Nn + kh * 64 + j) * Fn + ff];
    }
    __syncthreads();

    // 2) build all B_r = c_r (.) F^T (half), conflict-padded [f][72]
    for (int e = tid; e < NR * Fn; e += 512) {
        const float c = ch_coef[e];
        __half* dst = smB + e * 72;
        const float* src = Fst + (e & 63) * 72;
#pragma unroll
        for (int j = 0; j < 64; j += 2)
            *(__half2*)(dst + j) = __floats2half2_rn(c * src[j], c * src[j + 1]);
    }

    // distances -> xhat; thread covers row = tid>>2, 16 j's
    const int arow = tid >> 2;
    const int aj0 = (tid & 3) * 16;
    float xh[16], Tp[16], Tc[16];
    {
        const int ig = ih * 128 + arow;
        const float ix = smR[ig * 3], iy = smR[ig * 3 + 1], iz = smR[ig * 3 + 2];
#pragma unroll
        for (int e = 0; e < 16; ++e) {
            const int jg = kh * 64 + aj0 + e;
            const float dx = ix - smR[jg * 3];
            const float dy = iy - smR[jg * 3 + 1];
            const float dz = iz - smR[jg * 3 + 2];
            const float s = fmaf(dx, dx, fmaf(dy, dy, dz * dz));
            float d;
            asm("sqrt.approx.f32 %0, %1;" : "=f"(d) : "f"(s));  // sqrt(0)=0
            xh[e] = fmaf(d, 2.0f / D_MAX, -1.0f);
            Tp[e] = 1.0f;     // T_0
            Tc[e] = xh[e];    // T_1
        }
    }
    // A_0 = ones (T_0)
    {
        const __half2 one2 = __floats2half2_rn(1.0f, 1.0f);
        __half* dst = smA0 + arow * 72 + aj0;
#pragma unroll
        for (int e = 0; e < 16; e += 2) *(__half2*)(dst + e) = one2;
    }

    // mma setup
    const int m0 = (wid & 7) * 16;
    const int nh = wid >> 3;
    const uint32_t uB = smem_u32(smB);
    const uint32_t uA0 = smem_u32(smA0);
    const uint32_t uA1 = smem_u32(smA1);
    const uint32_t aoff = (uint32_t)(m0 + (lane & 7) + ((lane >> 3) & 1) * 8) * 144
                        + ((lane & 16) ? 16u : 0u);
    const int bl = lane & 15;
    const uint32_t boff = (uint32_t)(nh * 32 + (bl & 7)) * 144 + ((bl & 8) ? 16u : 0u);

    float acc[4][4] = {};

    int cur = 0;
    for (int r = 0; r < NR; ++r) {
        __syncthreads();  // A_r (and, at r==0, B) fully built
        const uint32_t uA = cur ? uA1 : uA0;
#pragma unroll
        for (int ks = 0; ks < 4; ++ks) {
            const uint32_t k0b = (uint32_t)ks * 32;  // 16 halves
            uint32_t a0, a1, a2, a3;
            asm volatile(
                "ldmatrix.sync.aligned.m8n8.x4.shared.b16 {%0,%1,%2,%3}, [%4];"
                : "=r"(a0), "=r"(a1), "=r"(a2), "=r"(a3)
                : "r"(uA + aoff + k0b));
#pragma unroll
            for (int nt = 0; nt < 4; ++nt) {
                uint32_t b0, b1;
                asm volatile(
                    "ldmatrix.sync.aligned.m8n8.x2.shared.b16 {%0,%1}, [%2];"
                    : "=r"(b0), "=r"(b1)
                    : "r"(uB + (uint32_t)r * 9216 + (uint32_t)nt * 1152 + boff + k0b));
                asm volatile(
                    "mma.sync.aligned.m16n8k16.row.col.f32.f16.f16.f32 "
                    "{%0,%1,%2,%3}, {%4,%5,%6,%7}, {%8,%9}, {%0,%1,%2,%3};"
                    : "+f"(acc[nt][0]), "+f"(acc[nt][1]),
                      "+f"(acc[nt][2]), "+f"(acc[nt][3])
                    : "r"(a0), "r"(a1), "r"(a2), "r"(a3), "r"(b0), "r"(b1));
            }
        }
        if (r < NR - 1) {
            // build A_{r+1} = Tc (== T_{r+1}), THEN advance the recurrence
            __half* dst = (cur ? smA0 : smA1) + arow * 72 + aj0;
#pragma unroll
            for (int e = 0; e < 16; e += 2) {
                *(__half2*)(dst + e) = __floats2half2_rn(Tc[e], Tc[e + 1]);
                const float t0 = fmaf(xh[e] + xh[e], Tc[e], -Tp[e]);
                const float t1 = fmaf(xh[e + 1] + xh[e + 1], Tc[e + 1], -Tp[e + 1]);
                Tp[e] = Tc[e]; Tc[e] = t0;
                Tp[e + 1] = Tc[e + 1]; Tc[e + 1] = t1;
            }
        }
        cur ^= 1;
    }

    // epilogue: c-frags -> partial_out
    const int mrow = ih * 128 + m0 + (lane >> 2);
    const int ncol = nh * 32 + (lane & 3) * 2;
    float* basep = partial_out + ((size_t)(kh * Bn + b) * Nn + mrow) * Fn;
#pragma unroll
    for (int nt = 0; nt < 4; ++nt) {
        *(float2*)(basep + nt * 8 + ncol) = make_float2(acc[nt][0], acc[nt][1]);
        *(float2*)(basep + 8 * Fn + nt * 8 + ncol) = make_float2(acc[nt][2], acc[nt][3]);
    }
}

// ---------------------------------------------------------------------------
// K4: sum the 4 j-quarter partials + softplus (float4).
// ---------------------------------------------------------------------------
__global__ void finalize_kernel(float* __restrict__ out) {
    const int i4 = blockIdx.x * 256 + threadIdx.x;
    const int SZ4 = (Bn * Nn * Fn) / 4;
    const float4* p = (const float4*)partial_out;
    const float4 a = p[i4], b = p[SZ4 + i4], c = p[2 * SZ4 + i4], d = p[3 * SZ4 + i4];
    float4 o;
    o.x = softplus_acc(a.x + b.x + c.x + d.x);
    o.y = softplus_acc(a.y + b.y + c.y + d.y);
    o.z = softplus_acc(a.z + b.z + c.z + d.z);
    o.w = softplus_acc(a.w + b.w + c.w + d.w);
    ((float4*)out)[i4] = o;
}

// ---------------------------------------------------------------------------
extern "C" void kernel_launch(void* const* d_in, const int* in_sizes, int n_in,
                              void* d_out, int out_size) {
    const float* r_batch = (const float*)d_in[0];  // [16,256,3]
    const float* f_batch = (const float*)d_in[1];  // [16,256,64]
    const float* w1 = (const float*)d_in[2];       // [128]
    const float* b1 = (const float*)d_in[3];       // [128]
    const float* W2 = (const float*)d_in[4];       // [128,64]
    const float* b2 = (const float*)d_in[5];       // [64]
    float* out = (float*)d_out;                    // [16,256,64]

    eval_nodes_kernel<<<NODES, Hn>>>(w1, b1, W2, b2);
    dct_kernel<<<1, NR * 64>>>();

    const int smem_bytes = 159744;  // 117KB B + 2x18KB A + 3KB r
    static bool attr_set = false;
    if (!attr_set) {
        cudaFuncSetAttribute(mp_mma_kernel,
                             cudaFuncAttributeMaxDynamicSharedMemorySize,
                             smem_bytes);
        attr_set = true;
    }
    mp_mma_kernel<<<128, 512, smem_bytes>>>(r_batch, f_batch);
    finalize_kernel<<<(Bn * Nn * Fn) / 1024, 256>>>(out);
}

// round 17
// speedup vs baseline: 1.4024x; 1.4024x over previous
#include <cuda_runtime.h>
#include <cuda_fp16.h>
#include <math.h>
#include <stdint.h>

#define Bn 16
#define Nn 256
#define Fn 64
#define Hn 128
#define D_MAX 1.7320508f
#define NODES 64
#define NR 10   // Chebyshev terms r = 0..9

__device__ float g_nodes[NODES * Fn];
__device__ float dct_w[NR * NODES];     // cos(r * theta_m), exact recurrence
__device__ float ch_coef[NR * Fn];
__device__ uint4 partial_raw[(4 * Bn * Nn * Fn) / 8];  // half partials, 16B units

__device__ __forceinline__ float softplus_acc(float x) {
    // matches jax.nn.softplus = logaddexp(x, 0), stable for all x
    return fmaxf(x, 0.0f) + log1pf(expf(-fabsf(x)));
}
__device__ __forceinline__ uint32_t smem_u32(const void* p) {
    uint32_t a;
    asm("{ .reg .u64 t; cvta.to.shared.u64 t, %1; cvt.u32.u64 %0, t; }"
        : "=r"(a) : "l"(p));
    return a;
}

// ---------------------------------------------------------------------------
// K1: g_f at 64 Chebyshev nodes + exact DCT weights. grid = NODES, block = Hn.
// ---------------------------------------------------------------------------
__global__ void eval_nodes_kernel(const float* __restrict__ w1,
                                  const float* __restrict__ b1,
                                  const float* __restrict__ W2,
                                  const float* __restrict__ b2) {
    __shared__ float u[Hn];
    const int m = blockIdx.x, h = threadIdx.x;
    const float theta = ((float)m + 0.5f) * (3.14159265358979f / (float)NODES);
    const float x = cosf(theta);
    const float d = (x + 1.0f) * (D_MAX * 0.5f);
    u[h] = softplus_acc(fmaf(d, w1[h], b1[h]));
    __syncthreads();
    if (h < Fn) {
        float acc = b2[h];
#pragma unroll
        for (int hh = 0; hh < Hn; ++hh)
            acc = fmaf(u[hh], W2[hh * Fn + h], acc);
        g_nodes[m * Fn + h] = softplus_acc(acc);
    } else if (h == Fn) {
        // dct_w[r][m] = cos(r*theta_m) = T_r(x), exact Chebyshev recurrence
        float c0 = 1.0f, c1 = x;
        dct_w[0 * NODES + m] = 1.0f;
        dct_w[1 * NODES + m] = x;
#pragma unroll
        for (int r = 2; r < NR; ++r) {
            const float c2 = fmaf(x + x, c1, -c0);
            dct_w[r * NODES + m] = c2;
            c0 = c1; c1 = c2;
        }
    }
}

// ---------------------------------------------------------------------------
// K2: DCT fit via precomputed weights. grid = NR*Fn/128 = 5, block = 128.
// ---------------------------------------------------------------------------
__global__ void dct_kernel() {
    const int tid = blockIdx.x * 128 + threadIdx.x;   // 0..639
    const int r = tid >> 6, ff = tid & 63;
    float s = 0.0f;
#pragma unroll 8
    for (int m = 0; m < NODES; ++m)
        s = fmaf(g_nodes[m * Fn + ff], dct_w[r * NODES + m], s);
    ch_coef[tid] = s * ((r == 0) ? (1.0f / NODES) : (2.0f / NODES));
}

// ---------------------------------------------------------------------------
// K3: main HMMA kernel. grid = 128 = b(16) x ih(2) x kh(4), block = 512.
// 10 accumulating M=128 N=64 K=64 f16 GEMMs via mma.sync.m16n8k16.
// A_r double-buffered (register Chebyshev recurrence); B_r precomputed.
// Partials written as HALF (all-positive sums; no cancellation).
// ---------------------------------------------------------------------------
__global__ __launch_bounds__(512, 1) void mp_mma_kernel(
    const float* __restrict__ rg, const float* __restrict__ fg) {
    extern __shared__ __align__(16) char sm[];
    __half* smB = (__half*)sm;                      // NR*64 rows * 144B = 92160
    __half* smA0 = (__half*)(sm + 92160);           // 128 * 144B = 18432
    __half* smA1 = (__half*)(sm + 110592);          // 18432
    float* Fst = (float*)(sm + 110592);             // staging [f][72] f32 (= A1)
    float* smR = (float*)(sm + 129024);              // 768 floats

    const int tid = threadIdx.x;
    const int wid = tid >> 5, lane = tid & 31;
    const int cta = blockIdx.x;
    const int b = cta >> 3, ih = (cta >> 2) & 1, kh = cta & 3;

    // stage r[b] + F quarter transposed to [f][72]
    for (int e = tid; e < Nn * 3; e += 512) smR[e] = rg[b * Nn * 3 + e];
    for (int e = tid; e < 64 * 64; e += 512) {
        const int j = e >> 6, ff = e & 63;
        Fst[ff * 72 + j] = fg[((size_t)b * Nn + kh * 64 + j) * Fn + ff];
    }
    __syncthreads();

    // all B_r = c_r (.) F^T (half), 144B-padded rows
    for (int e = tid; e < NR * Fn; e += 512) {
        const float c = ch_coef[e];
        __half* dst = smB + e * 72;
        const float* src = Fst + (e & 63) * 72;
#pragma unroll
        for (int j = 0; j < 64; j += 2)
            *(__half2*)(dst + j) = __floats2half2_rn(c * src[j], c * src[j + 1]);
    }

    // distances -> xhat; thread: row = tid>>2, 16 j's
    const int arow = tid >> 2;
    const int aj0 = (tid & 3) * 16;
    float xh[16], Tp[16], Tc[16];
    {
        const int ig = ih * 128 + arow;
        const float ix = smR[ig * 3], iy = smR[ig * 3 + 1], iz = smR[ig * 3 + 2];
#pragma unroll
        for (int e = 0; e < 16; ++e) {
            const int jg = kh * 64 + aj0 + e;
            const float dx = ix - smR[jg * 3];
            const float dy = iy - smR[jg * 3 + 1];
            const float dz = iz - smR[jg * 3 + 2];
            const float s = fmaf(dx, dx, fmaf(dy, dy, dz * dz));
            float d;
            asm("sqrt.approx.f32 %0, %1;" : "=f"(d) : "f"(s));  // sqrt(0)=0
            xh[e] = fmaf(d, 2.0f / D_MAX, -1.0f);
            Tp[e] = 1.0f;     // T_0
            Tc[e] = xh[e];    // T_1
        }
    }
    {   // A_0 = ones
        const __half2 one2 = __floats2half2_rn(1.0f, 1.0f);
        __half* dst = smA0 + arow * 72 + aj0;
#pragma unroll
        for (int e = 0; e < 16; e += 2) *(__half2*)(dst + e) = one2;
    }

    const int m0 = (wid & 7) * 16;
    const int nh = wid >> 3;
    const uint32_t uB = smem_u32(smB);
    const uint32_t uA0 = smem_u32(smA0);
    const uint32_t uA1 = smem_u32(smA1);
    const uint32_t aoff = (uint32_t)(m0 + (lane & 7) + ((lane >> 3) & 1) * 8) * 144
                        + ((lane & 16) ? 16u : 0u);
    const int bl = lane & 15;
    const uint32_t boff = (uint32_t)(nh * 32 + (bl & 7)) * 144 + ((bl & 8) ? 16u : 0u);

    float acc[4][4] = {};

    int cur = 0;
    for (int r = 0; r < NR; ++r) {
        __syncthreads();  // A_r (and, at r==0, B) fully built
        const uint32_t uA = cur ? uA1 : uA0;
#pragma unroll
        for (int ks = 0; ks < 4; ++ks) {
            const uint32_t k0b = (uint32_t)ks * 32;
            uint32_t a0, a1, a2, a3;
            asm volatile(
                "ldmatrix.sync.aligned.m8n8.x4.shared.b16 {%0,%1,%2,%3}, [%4];"
                : "=r"(a0), "=r"(a1), "=r"(a2), "=r"(a3)
                : "r"(uA + aoff + k0b));
#pragma unroll
            for (int nt = 0; nt < 4; ++nt) {
                uint32_t b0, b1;
                asm volatile(
                    "ldmatrix.sync.aligned.m8n8.x2.shared.b16 {%0,%1}, [%2];"
                    : "=r"(b0), "=r"(b1)
                    : "r"(uB + (uint32_t)r * 9216 + (uint32_t)nt * 1152 + boff + k0b));
                asm volatile(
                    "mma.sync.aligned.m16n8k16.row.col.f32.f16.f16.f32 "
                    "{%0,%1,%2,%3}, {%4,%5,%6,%7}, {%8,%9}, {%0,%1,%2,%3};"
                    : "+f"(acc[nt][0]), "+f"(acc[nt][1]),
                      "+f"(acc[nt][2]), "+f"(acc[nt][3])
                    : "r"(a0), "r"(a1), "r"(a2), "r"(a3), "r"(b0), "r"(b1));
            }
        }
        if (r < NR - 1) {
            // write A_{r+1} = Tc (= T_{r+1}), THEN advance the recurrence
            __half* dst = (cur ? smA0 : smA1) + arow * 72 + aj0;
#pragma unroll
            for (int e = 0; e < 16; e += 2) {
                *(__half2*)(dst + e) = __floats2half2_rn(Tc[e], Tc[e + 1]);
                const float t0 = fmaf(xh[e] + xh[e], Tc[e], -Tp[e]);
                const float t1 = fmaf(xh[e + 1] + xh[e + 1], Tc[e + 1], -Tp[e + 1]);
                Tp[e] = Tc[e]; Tc[e] = t0;
                Tp[e + 1] = Tc[e + 1]; Tc[e + 1] = t1;
            }
        }
        cur ^= 1;
    }

    // epilogue: c-frags -> half partials
    const int mrow = ih * 128 + m0 + (lane >> 2);
    const int ncol = nh * 32 + (lane & 3) * 2;
    __half* basep = (__half*)partial_raw +
                    ((size_t)(kh * Bn + b) * Nn + mrow) * Fn;
#pragma unroll
    for (int nt = 0; nt < 4; ++nt) {
        *(__half2*)(basep + nt * 8 + ncol) =
            __floats2half2_rn(acc[nt][0], acc[nt][1]);
        *(__half2*)(basep + 8 * Fn + nt * 8 + ncol) =
            __floats2half2_rn(acc[nt][2], acc[nt][3]);
    }
}

// ---------------------------------------------------------------------------
// K4: sum the 4 half partial quarters + softplus. Thread = 8 outputs.
// grid = 128, block = 256.
// ---------------------------------------------------------------------------
__global__ void finalize_kernel(float* __restrict__ out) {
    const int i8 = blockIdx.x * 256 + threadIdx.x;      // uint4 = 8 halves
    const int SZ8 = (Bn * Nn * Fn) / 8;
    float s[8];
#pragma unroll
    for (int q = 0; q < 4; ++q) {
        const uint4 v = partial_raw[q * SZ8 + i8];
        const unsigned w[4] = {v.x, v.y, v.z, v.w};
#pragma unroll
        for (int p = 0; p < 4; ++p) {
            const float2 f2 = __half22float2(*(const __half2*)&w[p]);
            if (q == 0) { s[p * 2] = f2.x; s[p * 2 + 1] = f2.y; }
            else        { s[p * 2] += f2.x; s[p * 2 + 1] += f2.y; }
        }
    }
    float4 o0, o1;
    o0.x = softplus_acc(s[0]); o0.y = softplus_acc(s[1]);
    o0.z = softplus_acc(s[2]); o0.w = softplus_acc(s[3]);
    o1.x = softplus_acc(s[4]); o1.y = softplus_acc(s[5]);
    o1.z = softplus_acc(s[6]); o1.w = softplus_acc(s[7]);
    ((float4*)out)[i8 * 2] = o0;
    ((float4*)out)[i8 * 2 + 1] = o1;
}

// ---------------------------------------------------------------------------
extern "C" void kernel_launch(void* const* d_in, const int* in_sizes, int n_in,
                              void* d_out, int out_size) {
    const float* r_batch = (const float*)d_in[0];  // [16,256,3]
    const float* f_batch = (const float*)d_in[1];  // [16,256,64]
    const float* w1 = (const float*)d_in[2];       // [128]
    const float* b1 = (const float*)d_in[3];       // [128]
    const float* W2 = (const float*)d_in[4];       // [128,64]
    const float* b2 = (const float*)d_in[5];       // [64]
    float* out = (float*)d_out;                    // [16,256,64]

    eval_nodes_kernel<<<NODES, Hn>>>(w1, b1, W2, b2);
    dct_kernel<<<(NR * Fn) / 128, 128>>>();

    const int smem_bytes = 132096;  // 90KB B + 2x18KB A + 3KB r
    static bool attr_set = false;
    if (!attr_set) {
        cudaFuncSetAttribute(mp_mma_kernel,
                             cudaFuncAttributeMaxDynamicSharedMemorySize,
                             smem_bytes);
        attr_set = true;
    }
    mp_mma_kernel<<<128, 512, smem_bytes>>>(r_batch, f_batch);
    finalize_kernel<<<(Bn * Nn * Fn) / 2048, 256>>>(out);
}